// round 1
// baseline (speedup 1.0000x reference)
#include <cuda_runtime.h>

#define HW 1024
#define CDIM 256
#define NSIDE 8192    // B*HW = 8*1024
#define NTOT 16384    // both sides

// Scratch (device globals: no allocation allowed)
__device__ float g_Q[NTOT * CDIM];
__device__ float g_K[NTOT * CDIM];
__device__ float g_V[NTOT * CDIM];
__device__ float g_BM[NTOT * 16];     // per-row max over each kv block of 1024
__device__ float g_GW[4 * NSIDE];     // gate weights: 0=aa,1=bb,2=ab,3=ba
__device__ float g_P[128 * NTOT];     // projected V, transposed [o][n]

// ---------------------------------------------------------------------------
// QKV: out[n][o] = sum_c x[side][b][c][hw] * w[o][c] + bias[o]
// n = side*8192 + b*1024 + hw.  grid (512 n-tiles, 8 o-tiles, 3 qkv)
// ---------------------------------------------------------------------------
__global__ void qkv_kernel(const float* __restrict__ x4, const float* __restrict__ x3,
                           const float* __restrict__ wq, const float* __restrict__ bq,
                           const float* __restrict__ wk, const float* __restrict__ bk,
                           const float* __restrict__ wv, const float* __restrict__ bv) {
    const float* w; const float* bias; float* out;
    if (blockIdx.z == 0)      { w = wq; bias = bq; out = g_Q; }
    else if (blockIdx.z == 1) { w = wk; bias = bk; out = g_K; }
    else                      { w = wv; bias = bv; out = g_V; }
    int n0 = blockIdx.x * 32;
    int side = n0 >> 13;
    int rem = n0 & (NSIDE - 1);
    int b = rem >> 10;
    int hw0 = rem & (HW - 1);
    const float* x = (side ? x3 : x4) + b * CDIM * HW;
    int o0 = blockIdx.y * 32;

    __shared__ float Xs[32][33];   // [cc][nn]
    __shared__ float Ws[32][33];   // [cc][oo]
    int t = threadIdx.x;
    int lo = t & 31, hi = t >> 5;
    float acc[4] = {0.f, 0.f, 0.f, 0.f};

    for (int c0 = 0; c0 < CDIM; c0 += 32) {
        #pragma unroll
        for (int r = 0; r < 4; r++) {
            int cc = hi + 8 * r;
            Xs[cc][lo] = x[(c0 + cc) * HW + hw0 + lo];        // coalesced over hw
        }
        #pragma unroll
        for (int r = 0; r < 4; r++) {
            int oo = hi + 8 * r;
            Ws[lo][oo] = w[(o0 + oo) * CDIM + c0 + lo];       // coalesced over c
        }
        __syncthreads();
        #pragma unroll
        for (int cc = 0; cc < 32; cc++) {
            float wv_ = Ws[cc][lo];
            #pragma unroll
            for (int r = 0; r < 4; r++)
                acc[r] += Xs[cc][hi + 8 * r] * wv_;
        }
        __syncthreads();
    }
    float bb = bias[o0 + lo];
    #pragma unroll
    for (int r = 0; r < 4; r++)
        out[(n0 + hi + 8 * r) * CDIM + o0 + lo] = acc[r] + bb;   // coalesced over o
}

// ---------------------------------------------------------------------------
// S block-max: BM[i][kb] = max_{j in kb*1024..+1023} dot(Q[i,:], K[j,:])
// Block: 64 i-rows x one kv block (loops 16 j-tiles of 64). 256 thr, 4x4/thread.
// ---------------------------------------------------------------------------
__global__ void smax_kernel() {
    int i0 = blockIdx.x * 64;
    int kb = blockIdx.y;
    int jbase = kb * HW;
    int t = threadIdx.x;
    int tx = t & 15, ty = t >> 4;

    __shared__ float Qs[16][64];
    __shared__ float Ks[16][64];

    float rowmax[4] = {-1e30f, -1e30f, -1e30f, -1e30f};
    int lii = t >> 2;            // 0..63
    int lkk = (t & 3) * 4;       // 0,4,8,12

    for (int j0 = 0; j0 < HW; j0 += 64) {
        float acc[4][4];
        #pragma unroll
        for (int r = 0; r < 4; r++)
            #pragma unroll
            for (int c2 = 0; c2 < 4; c2++) acc[r][c2] = 0.f;

        for (int k0 = 0; k0 < CDIM; k0 += 16) {
            float4 qv = *(const float4*)&g_Q[(i0 + lii) * CDIM + k0 + lkk];
            Qs[lkk + 0][lii] = qv.x; Qs[lkk + 1][lii] = qv.y;
            Qs[lkk + 2][lii] = qv.z; Qs[lkk + 3][lii] = qv.w;
            float4 kv = *(const float4*)&g_K[(jbase + j0 + lii) * CDIM + k0 + lkk];
            Ks[lkk + 0][lii] = kv.x; Ks[lkk + 1][lii] = kv.y;
            Ks[lkk + 2][lii] = kv.z; Ks[lkk + 3][lii] = kv.w;
            __syncthreads();
            #pragma unroll
            for (int kk = 0; kk < 16; kk++) {
                float4 a4 = *(const float4*)&Qs[kk][ty * 4];
                float4 b4 = *(const float4*)&Ks[kk][tx * 4];
                float a[4] = {a4.x, a4.y, a4.z, a4.w};
                float bv[4] = {b4.x, b4.y, b4.z, b4.w};
                #pragma unroll
                for (int r = 0; r < 4; r++)
                    #pragma unroll
                    for (int c2 = 0; c2 < 4; c2++)
                        acc[r][c2] += a[r] * bv[c2];
            }
            __syncthreads();
        }
        #pragma unroll
        for (int r = 0; r < 4; r++)
            #pragma unroll
            for (int c2 = 0; c2 < 4; c2++)
                rowmax[r] = fmaxf(rowmax[r], acc[r][c2]);
    }

    __shared__ float red[64][17];
    #pragma unroll
    for (int r = 0; r < 4; r++) red[ty * 4 + r][tx] = rowmax[r];
    __syncthreads();
    if (t < 64) {
        float m = -1e30f;
        #pragma unroll
        for (int k = 0; k < 16; k++) m = fmaxf(m, red[t][k]);
        g_BM[(i0 + t) * 16 + kb] = m;
    }
}

// ---------------------------------------------------------------------------
// Gate: m = mean of 8 block-maxes * scale; softmax over 1024 per (gate,batch)
// gate ids: 0=aa(q:a,k:a) 1=bb 2=ab(q:a,k:b) 3=ba(q:b,k:a)
// ---------------------------------------------------------------------------
__global__ void gate_kernel() {
    int g = blockIdx.x >> 3;
    int b = blockIdx.x & 7;
    int side = (g == 0 || g == 2) ? 0 : 1;   // query side
    int kbb  = (g == 0 || g == 3) ? 0 : 8;   // key block base
    int irow = side * NSIDE + b * HW;
    int t = threadIdx.x;

    float vals[4];
    #pragma unroll
    for (int r = 0; r < 4; r++) {
        int hw = t + 256 * r;
        const float* bm = &g_BM[(irow + hw) * 16 + kbb];
        float s = 0.f;
        #pragma unroll
        for (int k = 0; k < 8; k++) s += bm[k];
        vals[r] = s * (0.0625f / 8.0f);      // mean/8 then *1/sqrt(256)
    }

    __shared__ float red[256];
    float mx = fmaxf(fmaxf(vals[0], vals[1]), fmaxf(vals[2], vals[3]));
    red[t] = mx; __syncthreads();
    for (int s2 = 128; s2 > 0; s2 >>= 1) {
        if (t < s2) red[t] = fmaxf(red[t], red[t + s2]);
        __syncthreads();
    }
    mx = red[0]; __syncthreads();

    float sum = 0.f;
    #pragma unroll
    for (int r = 0; r < 4; r++) { vals[r] = expf(vals[r] - mx); sum += vals[r]; }
    red[t] = sum; __syncthreads();
    for (int s2 = 128; s2 > 0; s2 >>= 1) {
        if (t < s2) red[t] += red[t + s2];
        __syncthreads();
    }
    float inv = 1.f / red[0];
    #pragma unroll
    for (int r = 0; r < 4; r++)
        g_GW[g * NSIDE + b * HW + t + 256 * r] = vals[r] * inv;
}

// ---------------------------------------------------------------------------
// P projection: P[o][n] = sum_c V[n][c] * w128[o][c]   (transposed output)
// ---------------------------------------------------------------------------
__global__ void pgemm_kernel(const float* __restrict__ w128) {
    int n0 = blockIdx.x * 32;
    int o0 = blockIdx.y * 32;
    __shared__ float Vs[32][33];  // [cc][nn]
    __shared__ float Ws[32][33];  // [cc][oo]
    int t = threadIdx.x;
    int lo = t & 31, hi = t >> 5;
    float acc[4] = {0.f, 0.f, 0.f, 0.f};

    for (int c0 = 0; c0 < CDIM; c0 += 32) {
        #pragma unroll
        for (int r = 0; r < 4; r++) {
            int nn = hi + 8 * r;
            Vs[lo][nn] = g_V[(n0 + nn) * CDIM + c0 + lo];
        }
        #pragma unroll
        for (int r = 0; r < 4; r++) {
            int oo = hi + 8 * r;
            Ws[lo][oo] = w128[(o0 + oo) * CDIM + c0 + lo];
        }
        __syncthreads();
        #pragma unroll
        for (int cc = 0; cc < 32; cc++) {
            float vv = Vs[cc][lo];
            #pragma unroll
            for (int r = 0; r < 4; r++) acc[r] += Ws[cc][hi + 8 * r] * vv;
        }
        __syncthreads();
    }
    #pragma unroll
    for (int r = 0; r < 4; r++)
        g_P[(o0 + hi + 8 * r) * NTOT + n0 + lo] = acc[r];   // coalesced over n
}

// ---------------------------------------------------------------------------
// Final: out[b][ch][hw];  ch/128 -> branch (0:x34 1:a_x4 2:x43 3:b_x3)
// out = gate * P + b128  (tail softmax in reference is identity)
// ---------------------------------------------------------------------------
__global__ void final_kernel(const float* __restrict__ b128, float* __restrict__ out) {
    int idx = blockIdx.x * 256 + threadIdx.x;
    int hw = idx & (HW - 1);
    int ch = (idx >> 10) & 511;
    int b = idx >> 19;
    int n = b * HW + hw;
    int br = ch >> 7;
    int o = ch & 127;
    int gidx  = (br == 0) ? 3 : (br == 1) ? 0 : (br == 2) ? 2 : 1;
    int pside = (br < 2) ? 0 : 1;   // av for x34/a_x4, bv for x43/b_x3
    float gv = g_GW[gidx * NSIDE + n];
    float pv = g_P[o * NTOT + pside * NSIDE + n];
    out[idx] = gv * pv + b128[o];
}

extern "C" void kernel_launch(void* const* d_in, const int* in_sizes, int n_in,
                              void* d_out, int out_size) {
    const float* x4   = (const float*)d_in[0];
    const float* x3   = (const float*)d_in[1];
    const float* wq   = (const float*)d_in[2];
    const float* bq   = (const float*)d_in[3];
    const float* wk   = (const float*)d_in[4];
    const float* bk   = (const float*)d_in[5];
    const float* wv   = (const float*)d_in[6];
    const float* bv   = (const float*)d_in[7];
    const float* w128 = (const float*)d_in[8];
    const float* b128 = (const float*)d_in[9];
    float* out = (float*)d_out;

    qkv_kernel<<<dim3(512, 8, 3), 256>>>(x4, x3, wq, bq, wk, bk, wv, bv);
    smax_kernel<<<dim3(256, 16), 256>>>();
    gate_kernel<<<32, 256>>>();
    pgemm_kernel<<<dim3(512, 4), 256>>>(w128);
    final_kernel<<<16384, 256>>>(b128, out);
}

// round 3
// speedup vs baseline: 4.5452x; 4.5452x over previous
#include <cuda_runtime.h>
#include <cstdint>

#define HW 1024
#define CDIM 256
#define NSIDE 8192
#define NTOT 16384

// -------- scratch (device globals; no allocation allowed) --------
__device__ float g_Q[NTOT * CDIM];
__device__ float g_K[NTOT * CDIM];
__device__ float g_V[NTOT * CDIM];
__device__ float g_WT[3 * CDIM * CDIM];   // transposed qkv weights [c][o]
__device__ float g_BM[NTOT * 16];
__device__ float g_GW[4 * NSIDE];
__device__ float g_P[128 * NTOT];

// ======================= helpers =======================
__device__ __forceinline__ uint32_t smem_u32(const void* p) {
    uint32_t a;
    asm("{ .reg .u64 t; cvta.to.shared.u64 t, %1; cvt.u32.u64 %0, t; }"
        : "=r"(a) : "l"(p));
    return a;
}
__device__ __forceinline__ void cp_async16(uint32_t dst, const void* src) {
    asm volatile("cp.async.cg.shared.global [%0], [%1], 16;" :: "r"(dst), "l"(src) : "memory");
}
#define CP_COMMIT() asm volatile("cp.async.commit_group;" ::: "memory")
#define CP_WAIT(n)  asm volatile("cp.async.wait_group %0;" :: "n"(n) : "memory")

__device__ __forceinline__ float f2tf32(float f) {
    uint32_t u;
    asm("cvt.rna.tf32.f32 %0, %1;" : "=r"(u) : "f"(f));
    return __uint_as_float(u);
}

// ===========================================================================
// transpose weights: g_WT[m][c][o] = w_m[o][c]
// ===========================================================================
__global__ void transpose_w_kernel(const float* __restrict__ wq,
                                   const float* __restrict__ wk,
                                   const float* __restrict__ wv) {
    int m = blockIdx.y, c = blockIdx.x, o = threadIdx.x;
    const float* w = (m == 0) ? wq : (m == 1) ? wk : wv;
    g_WT[m * 65536 + c * 256 + o] = w[o * 256 + c];
}

// ===========================================================================
// QKV: out[n][o] = sum_c x[.][c][hw] wT[c][o] + b[o]; 64x64 tile, 4x4/thread
// Q and K outputs are rounded to tf32 so the smax mainloop needs no converts.
// ===========================================================================
__global__ void qkv_kernel(const float* __restrict__ x4, const float* __restrict__ x3,
                           const float* __restrict__ bq, const float* __restrict__ bk,
                           const float* __restrict__ bv) {
    int m = blockIdx.z;
    float* out = (m == 0) ? g_Q : (m == 1) ? g_K : g_V;
    const float* bias = (m == 0) ? bq : (m == 1) ? bk : bv;
    const float* wT = &g_WT[m * 65536];
    int n0 = blockIdx.x * 64;
    int side = n0 >> 13;
    int rem = n0 & (NSIDE - 1);
    int b = rem >> 10;
    int hw0 = rem & (HW - 1);
    const float* x = (side ? x3 : x4) + b * CDIM * HW;
    int o0 = blockIdx.y * 64;

    __shared__ float Xs[16][64];
    __shared__ float Ws[16][64];
    int t = threadIdx.x;
    int tx = t & 15, ty = t >> 4;
    float acc[4][4] = {};

    for (int c0 = 0; c0 < CDIM; c0 += 16) {
        #pragma unroll
        for (int r = 0; r < 4; r++) {
            int idx = r * 256 + t;
            int cc = idx >> 6, nn = idx & 63;
            Xs[cc][nn] = x[(c0 + cc) * HW + hw0 + nn];
            Ws[cc][nn] = wT[(c0 + cc) * 256 + o0 + nn];
        }
        __syncthreads();
        #pragma unroll
        for (int kk = 0; kk < 16; kk++) {
            float4 a4 = *(const float4*)&Xs[kk][ty * 4];
            float4 b4 = *(const float4*)&Ws[kk][tx * 4];
            float a[4] = {a4.x, a4.y, a4.z, a4.w};
            float bb[4] = {b4.x, b4.y, b4.z, b4.w};
            #pragma unroll
            for (int r = 0; r < 4; r++)
                #pragma unroll
                for (int c2 = 0; c2 < 4; c2++)
                    acc[r][c2] += a[r] * bb[c2];
        }
        __syncthreads();
    }
    bool tf = (m < 2);
    #pragma unroll
    for (int r = 0; r < 4; r++) {
        float4 o4;
        o4.x = acc[r][0] + bias[o0 + tx * 4 + 0];
        o4.y = acc[r][1] + bias[o0 + tx * 4 + 1];
        o4.z = acc[r][2] + bias[o0 + tx * 4 + 2];
        o4.w = acc[r][3] + bias[o0 + tx * 4 + 3];
        if (tf) { o4.x = f2tf32(o4.x); o4.y = f2tf32(o4.y);
                  o4.z = f2tf32(o4.z); o4.w = f2tf32(o4.w); }
        *(float4*)&out[(n0 + ty * 4 + r) * CDIM + o0 + tx * 4] = o4;
    }
}

// ===========================================================================
// Tensor-core S block-max via mma.sync m16n8k8 tf32.
// CTA: 128 q-rows x one kv block of 1024 keys. 256 threads = 8 warps (4x2).
// Q (128x256) fully resident in SMEM (stride 260, conflict-free frag loads).
// K streamed in 16KB chunks (128 keys x 32 k), 4-buffer cp.async pipeline.
// ===========================================================================
#define QS 260
#define KS 36
#define KCHUNK_FLOATS (128 * KS)      // 4608
#define SMAX_SMEM ((128 * QS + 4 * KCHUNK_FLOATS) * 4)   // 206848 B

__device__ __forceinline__ void load_k_chunk(float* kbuf, int jbase, int cidx) {
    int jc = cidx >> 3, kc = cidx & 7;
    const float* src = &g_K[(jbase + jc * 128) * CDIM + kc * 32];
    uint32_t base = smem_u32(kbuf);
    int t = threadIdx.x;
    #pragma unroll
    for (int i = 0; i < 4; i++) {
        int s = t + i * 256;          // 1024 16B segments
        int row = s >> 3, c16 = s & 7;
        cp_async16(base + (uint32_t)(row * (KS * 4) + c16 * 16),
                   src + row * CDIM + c16 * 4);
    }
    CP_COMMIT();
}

__global__ void __launch_bounds__(256, 1) smax_kernel() {
    extern __shared__ float sm[];
    float* Qs = sm;                           // 128*260
    float* Ks = sm + 128 * QS;                // 4 chunk buffers

    int t = threadIdx.x;
    int lane = t & 31;
    int wid = t >> 5;
    int wr = wid >> 1;          // 0..3: row group of 32
    int wc = wid & 1;           // 0..1: key half of 64
    int grp = lane >> 2;        // 0..7
    int qid = lane & 3;         // 0..3

    int i0 = blockIdx.x * 128;
    int kb = blockIdx.y;
    int jbase = kb * HW;

    // prologue: 3 K chunks in flight
    load_k_chunk(Ks + 0 * KCHUNK_FLOATS, jbase, 0);
    load_k_chunk(Ks + 1 * KCHUNK_FLOATS, jbase, 1);
    load_k_chunk(Ks + 2 * KCHUNK_FLOATS, jbase, 2);

    // Q tile -> SMEM (overlaps with cp.async)
    #pragma unroll
    for (int i = 0; i < 32; i++) {
        int idx = t + i * 256;        // 8192 float4
        int row = idx >> 6, c4 = idx & 63;
        *(float4*)&Qs[row * QS + c4 * 4] =
            *(const float4*)&g_Q[(i0 + row) * CDIM + c4 * 4];
    }

    float rmax[2][2] = {{-1e30f, -1e30f}, {-1e30f, -1e30f}};
    float acc[2][8][4];

    for (int cidx = 0; cidx < 64; cidx++) {
        if (cidx <= 61) { CP_WAIT(2); }
        else if (cidx == 62) { CP_WAIT(1); }
        else { CP_WAIT(0); }
        __syncthreads();

        int kc = cidx & 7;
        const float* kbuf = Ks + (cidx & 3) * KCHUNK_FLOATS;

        if (kc == 0) {
            #pragma unroll
            for (int rt = 0; rt < 2; rt++)
                #pragma unroll
                for (int nt = 0; nt < 8; nt++)
                    #pragma unroll
                    for (int r = 0; r < 4; r++) acc[rt][nt][r] = 0.f;
        }

        #pragma unroll
        for (int s = 0; s < 4; s++) {
            int kcol = kc * 32 + s * 8;
            uint32_t a[2][4];
            #pragma unroll
            for (int rt = 0; rt < 2; rt++) {
                const float* q0 = &Qs[(wr * 32 + rt * 16 + grp) * QS + kcol + qid];
                a[rt][0] = __float_as_uint(q0[0]);
                a[rt][1] = __float_as_uint(q0[8 * QS]);
                a[rt][2] = __float_as_uint(q0[4]);
                a[rt][3] = __float_as_uint(q0[8 * QS + 4]);
            }
            #pragma unroll
            for (int nt = 0; nt < 8; nt++) {
                const float* kp = &kbuf[(wc * 64 + nt * 8 + grp) * KS + s * 8 + qid];
                uint32_t b0 = __float_as_uint(kp[0]);
                uint32_t b1 = __float_as_uint(kp[4]);
                #pragma unroll
                for (int rt = 0; rt < 2; rt++) {
                    asm volatile(
                        "mma.sync.aligned.m16n8k8.row.col.f32.tf32.tf32.f32 "
                        "{%0,%1,%2,%3}, {%4,%5,%6,%7}, {%8,%9}, {%0,%1,%2,%3};"
                        : "+f"(acc[rt][nt][0]), "+f"(acc[rt][nt][1]),
                          "+f"(acc[rt][nt][2]), "+f"(acc[rt][nt][3])
                        : "r"(a[rt][0]), "r"(a[rt][1]), "r"(a[rt][2]), "r"(a[rt][3]),
                          "r"(b0), "r"(b1));
                }
            }
        }

        if (cidx + 3 < 64)
            load_k_chunk(Ks + ((cidx + 3) & 3) * KCHUNK_FLOATS, jbase, cidx + 3);

        if (kc == 7) {
            #pragma unroll
            for (int rt = 0; rt < 2; rt++)
                #pragma unroll
                for (int nt = 0; nt < 8; nt++) {
                    rmax[rt][0] = fmaxf(rmax[rt][0], fmaxf(acc[rt][nt][0], acc[rt][nt][1]));
                    rmax[rt][1] = fmaxf(rmax[rt][1], fmaxf(acc[rt][nt][2], acc[rt][nt][3]));
                }
        }
    }

    // combine across lane%4 (same row, different frag cols)
    #pragma unroll
    for (int rt = 0; rt < 2; rt++)
        #pragma unroll
        for (int h = 0; h < 2; h++) {
            float v = rmax[rt][h];
            v = fmaxf(v, __shfl_xor_sync(0xFFFFFFFF, v, 1));
            v = fmaxf(v, __shfl_xor_sync(0xFFFFFFFF, v, 2));
            rmax[rt][h] = v;
        }

    __syncthreads();   // done reading Qs; reuse as reduction scratch
    if (qid == 0) {
        #pragma unroll
        for (int rt = 0; rt < 2; rt++)
            #pragma unroll
            for (int h = 0; h < 2; h++) {
                int row = wr * 32 + rt * 16 + h * 8 + grp;
                Qs[wc * 128 + row] = rmax[rt][h];
            }
    }
    __syncthreads();
    if (t < 128)
        g_BM[(i0 + t) * 16 + kb] = fmaxf(Qs[t], Qs[128 + t]);
}

// ===========================================================================
// Gate: softmax over 1024 of mean-of-8-blockmax * scale
// ===========================================================================
__global__ void gate_kernel() {
    int g = blockIdx.x >> 3;
    int b = blockIdx.x & 7;
    int side = (g == 0 || g == 2) ? 0 : 1;
    int kbb  = (g == 0 || g == 3) ? 0 : 8;
    int irow = side * NSIDE + b * HW;
    int t = threadIdx.x;

    float vals[4];
    #pragma unroll
    for (int r = 0; r < 4; r++) {
        int hw = t + 256 * r;
        const float* bm = &g_BM[(irow + hw) * 16 + kbb];
        float s = 0.f;
        #pragma unroll
        for (int k = 0; k < 8; k++) s += bm[k];
        vals[r] = s * (0.0625f / 8.0f);
    }
    __shared__ float red[256];
    float mx = fmaxf(fmaxf(vals[0], vals[1]), fmaxf(vals[2], vals[3]));
    red[t] = mx; __syncthreads();
    for (int s2 = 128; s2 > 0; s2 >>= 1) {
        if (t < s2) red[t] = fmaxf(red[t], red[t + s2]);
        __syncthreads();
    }
    mx = red[0]; __syncthreads();
    float sum = 0.f;
    #pragma unroll
    for (int r = 0; r < 4; r++) { vals[r] = expf(vals[r] - mx); sum += vals[r]; }
    red[t] = sum; __syncthreads();
    for (int s2 = 128; s2 > 0; s2 >>= 1) {
        if (t < s2) red[t] += red[t + s2];
        __syncthreads();
    }
    float inv = 1.f / red[0];
    #pragma unroll
    for (int r = 0; r < 4; r++)
        g_GW[g * NSIDE + b * HW + t + 256 * r] = vals[r] * inv;
}

// ===========================================================================
// P projection: P[o][n] = sum_c V[n][c] * w128[o][c]
// ===========================================================================
__global__ void pgemm_kernel(const float* __restrict__ w128) {
    int n0 = blockIdx.x * 32;
    int o0 = blockIdx.y * 32;
    __shared__ float Vs[32][33];
    __shared__ float Ws[32][33];
    int t = threadIdx.x;
    int lo = t & 31, hi = t >> 5;
    float acc[4] = {0.f, 0.f, 0.f, 0.f};

    for (int c0 = 0; c0 < CDIM; c0 += 32) {
        #pragma unroll
        for (int r = 0; r < 4; r++) {
            int nn = hi + 8 * r;
            Vs[lo][nn] = g_V[(n0 + nn) * CDIM + c0 + lo];
        }
        #pragma unroll
        for (int r = 0; r < 4; r++) {
            int oo = hi + 8 * r;
            Ws[lo][oo] = w128[(o0 + oo) * CDIM + c0 + lo];
        }
        __syncthreads();
        #pragma unroll
        for (int cc = 0; cc < 32; cc++) {
            float vv = Vs[cc][lo];
            #pragma unroll
            for (int r = 0; r < 4; r++) acc[r] += Ws[cc][hi + 8 * r] * vv;
        }
        __syncthreads();
    }
    #pragma unroll
    for (int r = 0; r < 4; r++)
        g_P[(o0 + hi + 8 * r) * NTOT + n0 + lo] = acc[r];
}

// ===========================================================================
// Final: out = gate * P + b128
// ===========================================================================
__global__ void final_kernel(const float* __restrict__ b128, float* __restrict__ out) {
    int idx = blockIdx.x * 256 + threadIdx.x;
    int hw = idx & (HW - 1);
    int ch = (idx >> 10) & 511;
    int b = idx >> 19;
    int n = b * HW + hw;
    int br = ch >> 7;
    int o = ch & 127;
    int gidx  = (br == 0) ? 3 : (br == 1) ? 0 : (br == 2) ? 2 : 1;
    int pside = (br < 2) ? 0 : 1;
    float gv = g_GW[gidx * NSIDE + n];
    float pv = g_P[o * NTOT + pside * NSIDE + n];
    out[idx] = gv * pv + b128[o];
}

extern "C" void kernel_launch(void* const* d_in, const int* in_sizes, int n_in,
                              void* d_out, int out_size) {
    const float* x4   = (const float*)d_in[0];
    const float* x3   = (const float*)d_in[1];
    const float* wq   = (const float*)d_in[2];
    const float* bq   = (const float*)d_in[3];
    const float* wk   = (const float*)d_in[4];
    const float* bk   = (const float*)d_in[5];
    const float* wv   = (const float*)d_in[6];
    const float* bv   = (const float*)d_in[7];
    const float* w128 = (const float*)d_in[8];
    const float* b128 = (const float*)d_in[9];
    float* out = (float*)d_out;

    static int smem_set = 0;
    if (!smem_set) {
        cudaFuncSetAttribute(smax_kernel,
                             cudaFuncAttributeMaxDynamicSharedMemorySize, SMAX_SMEM);
        smem_set = 1;
    }

    transpose_w_kernel<<<dim3(256, 3), 256>>>(wq, wk, wv);
    qkv_kernel<<<dim3(256, 4, 3), 256>>>(x4, x3, bq, bk, bv);
    smax_kernel<<<dim3(128, 16), 256, SMAX_SMEM>>>();
    gate_kernel<<<32, 256>>>();
    pgemm_kernel<<<dim3(512, 4), 256>>>(w128);
    final_kernel<<<16384, 256>>>(b128, out);
}

// round 4
// speedup vs baseline: 8.0331x; 1.7674x over previous
#include <cuda_runtime.h>
#include <cuda_fp16.h>
#include <cstdint>

#define HW 1024
#define CDIM 256
#define NSIDE 8192
#define NTOT 16384

// -------- scratch (device globals; no allocation allowed) --------
__device__ __half g_Xh[NTOT * CDIM];      // x transposed to [n][c], fp16
__device__ __half g_Whqk[512 * CDIM];     // [wq;wk] as [o][c], fp16
__device__ __half g_Qh[NTOT * CDIM];
__device__ __half g_Kh[NTOT * CDIM];
__device__ float  g_V[NTOT * CDIM];
__device__ float  g_WT[CDIM * CDIM];      // wv transposed [c][o]
__device__ float  g_BM[NTOT * 16];
__device__ float  g_GW[4 * NSIDE];
__device__ float  g_P[128 * NTOT];

// ======================= helpers =======================
__device__ __forceinline__ uint32_t smem_u32(const void* p) {
    uint32_t a;
    asm("{ .reg .u64 t; cvta.to.shared.u64 t, %1; cvt.u32.u64 %0, t; }"
        : "=r"(a) : "l"(p));
    return a;
}
__device__ __forceinline__ void cp_async16(uint32_t dst, const void* src) {
    asm volatile("cp.async.cg.shared.global [%0], [%1], 16;" :: "r"(dst), "l"(src) : "memory");
}
#define CP_COMMIT() asm volatile("cp.async.commit_group;" ::: "memory")
#define CP_WAIT(n)  asm volatile("cp.async.wait_group %0;" :: "n"(n) : "memory")

__device__ __forceinline__ void mma_fp16(float* c, const uint32_t* a,
                                         uint32_t b0, uint32_t b1) {
    asm volatile(
        "mma.sync.aligned.m16n8k16.row.col.f32.f16.f16.f32 "
        "{%0,%1,%2,%3}, {%4,%5,%6,%7}, {%8,%9}, {%0,%1,%2,%3};"
        : "+f"(c[0]), "+f"(c[1]), "+f"(c[2]), "+f"(c[3])
        : "r"(a[0]), "r"(a[1]), "r"(a[2]), "r"(a[3]), "r"(b0), "r"(b1));
}

// ===========================================================================
// wv transpose: g_WT[c][o] = wv[o][c]
// ===========================================================================
__global__ void transpose_wv_kernel(const float* __restrict__ wv) {
    int c = blockIdx.x, o = threadIdx.x;
    g_WT[c * 256 + o] = wv[o * 256 + c];
}

// ===========================================================================
// wq/wk -> fp16 [o][c], o in [0,512)
// ===========================================================================
__global__ void convert_wqk_kernel(const float* __restrict__ wq,
                                   const float* __restrict__ wk) {
    int o = blockIdx.x, c = threadIdx.x;
    float v = (o < 256) ? wq[o * 256 + c] : wk[(o - 256) * 256 + c];
    g_Whqk[o * 256 + c] = __float2half_rn(v);
}

// ===========================================================================
// x [b][c][hw] -> g_Xh [n][c] fp16 (tiled transpose)
// ===========================================================================
__global__ void convert_x_kernel(const float* __restrict__ x4,
                                 const float* __restrict__ x3) {
    __shared__ float tile[32][33];
    int z = blockIdx.z;
    int side = z >> 3, b = z & 7;
    const float* x = (side ? x3 : x4) + b * CDIM * HW;
    int hw0 = blockIdx.x * 32;
    int c0 = blockIdx.y * 32;
    int t = threadIdx.x;
    int lane = t & 31, ty = t >> 5;

    #pragma unroll
    for (int i = 0; i < 4; i++) {
        int cc = ty + i * 8;
        tile[cc][lane] = x[(c0 + cc) * HW + hw0 + lane];
    }
    __syncthreads();
    int nbase = side * NSIDE + b * HW + hw0;
    #pragma unroll
    for (int i = 0; i < 4; i++) {
        int hwr = ty + i * 8;
        g_Xh[(nbase + hwr) * 256 + c0 + lane] = __float2half_rn(tile[lane][hwr]);
    }
}

// ===========================================================================
// QK fp16 tensor GEMM: out[n][o] = sum_c Xh[n][c] * Whqk[o][c] + bias[o]
// CTA tile 128x128, K=256 fully resident. 256 thr = 8 warps (2m x 4n).
// by 0,1 -> Q cols 0..255 ; by 2,3 -> K cols 0..255.
// ===========================================================================
#define QKG_SMEM (2 * 128 * 264 * 2)   // 135168 B

__global__ void __launch_bounds__(256, 1) qk_gemm_kernel(const float* __restrict__ bq,
                                                         const float* __restrict__ bk) {
    extern __shared__ __half smh[];
    __half* Xs = smh;              // 128 x 264
    __half* Ws = smh + 128 * 264;
    int t = threadIdx.x, lane = t & 31, wid = t >> 5;
    int wm = wid >> 2, wn = wid & 3;
    int grp = lane >> 2, qid = lane & 3;
    int m0 = blockIdx.x * 128, o0 = blockIdx.y * 128;

    uint32_t xb = smem_u32(Xs), wb = smem_u32(Ws);
    #pragma unroll
    for (int i = 0; i < 16; i++) {
        int s = t + i * 256;
        int row = s >> 5, seg = s & 31;
        cp_async16(xb + row * 528 + seg * 16,
                   (const char*)&g_Xh[(m0 + row) * 256] + seg * 16);
        cp_async16(wb + row * 528 + seg * 16,
                   (const char*)&g_Whqk[(o0 + row) * 256] + seg * 16);
    }
    CP_COMMIT(); CP_WAIT(0);
    __syncthreads();

    float acc[4][4][4] = {};
    #pragma unroll
    for (int kk = 0; kk < 16; kk++) {
        uint32_t a[4][4];
        #pragma unroll
        for (int rt = 0; rt < 4; rt++) {
            const __half* q0 = &Xs[(wm * 64 + rt * 16 + grp) * 264 + kk * 16 + qid * 2];
            a[rt][0] = *(const uint32_t*)q0;
            a[rt][1] = *(const uint32_t*)(q0 + 8 * 264);
            a[rt][2] = *(const uint32_t*)(q0 + 8);
            a[rt][3] = *(const uint32_t*)(q0 + 8 * 264 + 8);
        }
        #pragma unroll
        for (int nt = 0; nt < 4; nt++) {
            const __half* kp = &Ws[(wn * 32 + nt * 8 + grp) * 264 + kk * 16 + qid * 2];
            uint32_t b0 = *(const uint32_t*)kp;
            uint32_t b1 = *(const uint32_t*)(kp + 8);
            #pragma unroll
            for (int rt = 0; rt < 4; rt++)
                mma_fp16(acc[rt][nt], a[rt], b0, b1);
        }
    }

    __half* dst = (blockIdx.y < 2) ? g_Qh : g_Kh;
    const float* bias = (blockIdx.y < 2) ? bq : bk;
    #pragma unroll
    for (int rt = 0; rt < 4; rt++)
        #pragma unroll
        for (int nt = 0; nt < 4; nt++) {
            int col = (o0 + wn * 32 + nt * 8 + qid * 2) & 255;
            float b0f = bias[col], b1f = bias[col + 1];
            int r0 = m0 + wm * 64 + rt * 16 + grp;
            __half2 h0 = __floats2half2_rn(acc[rt][nt][0] + b0f, acc[rt][nt][1] + b1f);
            __half2 h1 = __floats2half2_rn(acc[rt][nt][2] + b0f, acc[rt][nt][3] + b1f);
            *(__half2*)&dst[r0 * 256 + col] = h0;
            *(__half2*)&dst[(r0 + 8) * 256 + col] = h1;
        }
}

// ===========================================================================
// V projection (fp32 SIMT, accuracy-critical): g_V[n][o]
// ===========================================================================
__global__ void v_kernel(const float* __restrict__ x4, const float* __restrict__ x3,
                         const float* __restrict__ bv) {
    int n0 = blockIdx.x * 64;
    int side = n0 >> 13;
    int rem = n0 & (NSIDE - 1);
    int b = rem >> 10;
    int hw0 = rem & (HW - 1);
    const float* x = (side ? x3 : x4) + b * CDIM * HW;
    int o0 = blockIdx.y * 64;

    __shared__ float Xs[16][64];
    __shared__ float Ws[16][64];
    int t = threadIdx.x;
    int tx = t & 15, ty = t >> 4;
    float acc[4][4] = {};

    for (int c0 = 0; c0 < CDIM; c0 += 16) {
        #pragma unroll
        for (int r = 0; r < 4; r++) {
            int idx = r * 256 + t;
            int cc = idx >> 6, nn = idx & 63;
            Xs[cc][nn] = x[(c0 + cc) * HW + hw0 + nn];
            Ws[cc][nn] = g_WT[(c0 + cc) * 256 + o0 + nn];
        }
        __syncthreads();
        #pragma unroll
        for (int kk = 0; kk < 16; kk++) {
            float4 a4 = *(const float4*)&Xs[kk][ty * 4];
            float4 b4 = *(const float4*)&Ws[kk][tx * 4];
            float a[4] = {a4.x, a4.y, a4.z, a4.w};
            float bb[4] = {b4.x, b4.y, b4.z, b4.w};
            #pragma unroll
            for (int r = 0; r < 4; r++)
                #pragma unroll
                for (int c2 = 0; c2 < 4; c2++)
                    acc[r][c2] += a[r] * bb[c2];
        }
        __syncthreads();
    }
    #pragma unroll
    for (int r = 0; r < 4; r++) {
        float4 o4;
        o4.x = acc[r][0] + bv[o0 + tx * 4 + 0];
        o4.y = acc[r][1] + bv[o0 + tx * 4 + 1];
        o4.z = acc[r][2] + bv[o0 + tx * 4 + 2];
        o4.w = acc[r][3] + bv[o0 + tx * 4 + 3];
        *(float4*)&g_V[(n0 + ty * 4 + r) * CDIM + o0 + tx * 4] = o4;
    }
}

// ===========================================================================
// fp16 tensor-core S block-max.
// CTA: 128 q-rows x 1024 keys, 256 thr = 8 warps (4 row-groups x 2 key-halves).
// Q (128x256 fp16, stride 264) resident; K streamed in 8KB chunks
// (128 keys x 32 k fp16, stride 40), 4-buffer cp.async pipeline.
// ===========================================================================
#define QSH 264
#define KSH 40
#define KCH (128 * KSH)                               // halves per chunk
#define SMAX_SMEM (128 * QSH * 2 + 4 * KCH * 2 + 1024) // 109568 B

__device__ __forceinline__ void load_k_chunk_h(uint32_t kb_base, int jbase, int cidx) {
    int jc = cidx >> 3, kc = cidx & 7;
    const __half* src = &g_Kh[(jbase + jc * 128) * 256 + kc * 32];
    int t = threadIdx.x;
    #pragma unroll
    for (int i = 0; i < 2; i++) {
        int s = t + i * 256;
        int row = s >> 2, seg = s & 3;
        cp_async16(kb_base + (uint32_t)(row * 80 + seg * 16),
                   (const char*)(src + row * 256) + seg * 16);
    }
    CP_COMMIT();
}

__global__ void __launch_bounds__(256, 2) smax_kernel() {
    extern __shared__ char sm[];
    __half* Qs = (__half*)sm;                    // 128 x 264
    uint32_t qbase = smem_u32(sm);
    uint32_t kbase = qbase + 128 * QSH * 2;
    float* red = (float*)(sm + 128 * QSH * 2 + 4 * KCH * 2);

    int t = threadIdx.x, lane = t & 31, wid = t >> 5;
    int wr = wid >> 1, wc = wid & 1;
    int grp = lane >> 2, qid = lane & 3;
    int i0 = blockIdx.x * 128, kb = blockIdx.y, jbase = kb * HW;

    // group 0: Q tile
    #pragma unroll
    for (int i = 0; i < 16; i++) {
        int s = t + i * 256;
        int row = s >> 5, seg = s & 31;
        cp_async16(qbase + (uint32_t)(row * 528 + seg * 16),
                   (const char*)&g_Qh[(i0 + row) * 256] + seg * 16);
    }
    CP_COMMIT();
    load_k_chunk_h(kbase + 0 * KCH * 2, jbase, 0);
    load_k_chunk_h(kbase + 1 * KCH * 2, jbase, 1);
    load_k_chunk_h(kbase + 2 * KCH * 2, jbase, 2);

    float rmax[2][2] = {{-1e30f, -1e30f}, {-1e30f, -1e30f}};
    float acc[2][8][4];

    for (int c = 0; c < 64; c++) {
        if (c <= 61) { CP_WAIT(2); }
        else if (c == 62) { CP_WAIT(1); }
        else { CP_WAIT(0); }
        __syncthreads();

        int kc = c & 7;
        const __half* kbuf = (const __half*)(sm + 128 * QSH * 2 + (size_t)(c & 3) * KCH * 2);

        if (kc == 0) {
            #pragma unroll
            for (int rt = 0; rt < 2; rt++)
                #pragma unroll
                for (int nt = 0; nt < 8; nt++)
                    #pragma unroll
                    for (int r = 0; r < 4; r++) acc[rt][nt][r] = 0.f;
        }

        #pragma unroll
        for (int s = 0; s < 2; s++) {
            int kcol = kc * 32 + s * 16;
            uint32_t a[2][4];
            #pragma unroll
            for (int rt = 0; rt < 2; rt++) {
                const __half* q0 = &Qs[(wr * 32 + rt * 16 + grp) * QSH + kcol + qid * 2];
                a[rt][0] = *(const uint32_t*)q0;
                a[rt][1] = *(const uint32_t*)(q0 + 8 * QSH);
                a[rt][2] = *(const uint32_t*)(q0 + 8);
                a[rt][3] = *(const uint32_t*)(q0 + 8 * QSH + 8);
            }
            #pragma unroll
            for (int nt = 0; nt < 8; nt++) {
                const __half* kp = &kbuf[(wc * 64 + nt * 8 + grp) * KSH + s * 16 + qid * 2];
                uint32_t b0 = *(const uint32_t*)kp;
                uint32_t b1 = *(const uint32_t*)(kp + 8);
                #pragma unroll
                for (int rt = 0; rt < 2; rt++)
                    mma_fp16(acc[rt][nt], a[rt], b0, b1);
            }
        }

        if (c + 3 < 64)
            load_k_chunk_h(kbase + (uint32_t)((c + 3) & 3) * KCH * 2, jbase, c + 3);

        if (kc == 7) {
            #pragma unroll
            for (int rt = 0; rt < 2; rt++)
                #pragma unroll
                for (int nt = 0; nt < 8; nt++) {
                    rmax[rt][0] = fmaxf(rmax[rt][0], fmaxf(acc[rt][nt][0], acc[rt][nt][1]));
                    rmax[rt][1] = fmaxf(rmax[rt][1], fmaxf(acc[rt][nt][2], acc[rt][nt][3]));
                }
        }
    }

    #pragma unroll
    for (int rt = 0; rt < 2; rt++)
        #pragma unroll
        for (int h = 0; h < 2; h++) {
            float v = rmax[rt][h];
            v = fmaxf(v, __shfl_xor_sync(0xFFFFFFFF, v, 1));
            v = fmaxf(v, __shfl_xor_sync(0xFFFFFFFF, v, 2));
            rmax[rt][h] = v;
        }

    __syncthreads();
    if (qid == 0) {
        #pragma unroll
        for (int rt = 0; rt < 2; rt++)
            #pragma unroll
            for (int h = 0; h < 2; h++) {
                int row = wr * 32 + rt * 16 + h * 8 + grp;
                red[wc * 128 + row] = rmax[rt][h];
            }
    }
    __syncthreads();
    if (t < 128)
        g_BM[(i0 + t) * 16 + kb] = fmaxf(red[t], red[128 + t]);
}

// ===========================================================================
// Gate: softmax over 1024 of mean-of-8-blockmax * scale
// ===========================================================================
__global__ void gate_kernel() {
    int g = blockIdx.x >> 3;
    int b = blockIdx.x & 7;
    int side = (g == 0 || g == 2) ? 0 : 1;
    int kbb  = (g == 0 || g == 3) ? 0 : 8;
    int irow = side * NSIDE + b * HW;
    int t = threadIdx.x;

    float vals[4];
    #pragma unroll
    for (int r = 0; r < 4; r++) {
        int hw = t + 256 * r;
        const float* bm = &g_BM[(irow + hw) * 16 + kbb];
        float s = 0.f;
        #pragma unroll
        for (int k = 0; k < 8; k++) s += bm[k];
        vals[r] = s * (0.0625f / 8.0f);
    }
    __shared__ float red[256];
    float mx = fmaxf(fmaxf(vals[0], vals[1]), fmaxf(vals[2], vals[3]));
    red[t] = mx; __syncthreads();
    for (int s2 = 128; s2 > 0; s2 >>= 1) {
        if (t < s2) red[t] = fmaxf(red[t], red[t + s2]);
        __syncthreads();
    }
    mx = red[0]; __syncthreads();
    float sum = 0.f;
    #pragma unroll
    for (int r = 0; r < 4; r++) { vals[r] = expf(vals[r] - mx); sum += vals[r]; }
    red[t] = sum; __syncthreads();
    for (int s2 = 128; s2 > 0; s2 >>= 1) {
        if (t < s2) red[t] += red[t + s2];
        __syncthreads();
    }
    float inv = 1.f / red[0];
    #pragma unroll
    for (int r = 0; r < 4; r++)
        g_GW[g * NSIDE + b * HW + t + 256 * r] = vals[r] * inv;
}

// ===========================================================================
// P projection: P[o][n] = sum_c V[n][c] * w128[o][c]
// ===========================================================================
__global__ void pgemm_kernel(const float* __restrict__ w128) {
    int n0 = blockIdx.x * 32;
    int o0 = blockIdx.y * 32;
    __shared__ float Vs[32][33];
    __shared__ float Ws[32][33];
    int t = threadIdx.x;
    int lo = t & 31, hi = t >> 5;
    float acc[4] = {0.f, 0.f, 0.f, 0.f};

    for (int c0 = 0; c0 < CDIM; c0 += 32) {
        #pragma unroll
        for (int r = 0; r < 4; r++) {
            int nn = hi + 8 * r;
            Vs[lo][nn] = g_V[(n0 + nn) * CDIM + c0 + lo];
        }
        #pragma unroll
        for (int r = 0; r < 4; r++) {
            int oo = hi + 8 * r;
            Ws[lo][oo] = w128[(o0 + oo) * CDIM + c0 + lo];
        }
        __syncthreads();
        #pragma unroll
        for (int cc = 0; cc < 32; cc++) {
            float vv = Vs[cc][lo];
            #pragma unroll
            for (int r = 0; r < 4; r++) acc[r] += Ws[cc][hi + 8 * r] * vv;
        }
        __syncthreads();
    }
    #pragma unroll
    for (int r = 0; r < 4; r++)
        g_P[(o0 + hi + 8 * r) * NTOT + n0 + lo] = acc[r];
}

// ===========================================================================
// Final: out = gate * P + b128
// ===========================================================================
__global__ void final_kernel(const float* __restrict__ b128, float* __restrict__ out) {
    int idx = blockIdx.x * 256 + threadIdx.x;
    int hw = idx & (HW - 1);
    int ch = (idx >> 10) & 511;
    int b = idx >> 19;
    int n = b * HW + hw;
    int br = ch >> 7;
    int o = ch & 127;
    int gidx  = (br == 0) ? 3 : (br == 1) ? 0 : (br == 2) ? 2 : 1;
    int pside = (br < 2) ? 0 : 1;
    float gv = g_GW[gidx * NSIDE + n];
    float pv = g_P[o * NTOT + pside * NSIDE + n];
    out[idx] = gv * pv + b128[o];
}

extern "C" void kernel_launch(void* const* d_in, const int* in_sizes, int n_in,
                              void* d_out, int out_size) {
    const float* x4   = (const float*)d_in[0];
    const float* x3   = (const float*)d_in[1];
    const float* wq   = (const float*)d_in[2];
    const float* bq   = (const float*)d_in[3];
    const float* wk   = (const float*)d_in[4];
    const float* bk   = (const float*)d_in[5];
    const float* wv   = (const float*)d_in[6];
    const float* bv   = (const float*)d_in[7];
    const float* w128 = (const float*)d_in[8];
    const float* b128 = (const float*)d_in[9];
    float* out = (float*)d_out;

    static int attr_set = 0;
    if (!attr_set) {
        cudaFuncSetAttribute(smax_kernel,
                             cudaFuncAttributeMaxDynamicSharedMemorySize, SMAX_SMEM);
        cudaFuncSetAttribute(qk_gemm_kernel,
                             cudaFuncAttributeMaxDynamicSharedMemorySize, QKG_SMEM);
        attr_set = 1;
    }

    transpose_wv_kernel<<<256, 256>>>(wv);
    convert_wqk_kernel<<<512, 256>>>(wq, wk);
    convert_x_kernel<<<dim3(32, 8, 16), 256>>>(x4, x3);
    qk_gemm_kernel<<<dim3(128, 4), 256, QKG_SMEM>>>(bq, bk);
    v_kernel<<<dim3(256, 4), 256>>>(x4, x3, bv);
    smax_kernel<<<dim3(128, 16), 256, SMAX_SMEM>>>();
    gate_kernel<<<32, 256>>>();
    pgemm_kernel<<<dim3(512, 4), 256>>>(w128);
    final_kernel<<<16384, 256>>>(b128, out);
}

// round 5
// speedup vs baseline: 8.8959x; 1.1074x over previous
#include <cuda_runtime.h>
#include <cuda_fp16.h>
#include <cstdint>

#define HW 1024
#define CDIM 256
#define NSIDE 8192
#define NTOT 16384

// -------- scratch (device globals; no allocation allowed) --------
__device__ __half g_Xh[NTOT * CDIM];      // x transposed to [n][c], fp16
__device__ __half g_Whqk[512 * CDIM];     // [wq;wk] as [o][c], fp16
__device__ __half g_Qh[NTOT * CDIM];
__device__ __half g_Kh[NTOT * CDIM];
__device__ float  g_wcT[CDIM * 128];      // (w128 @ wv) transposed [c][o]
__device__ float  g_pb2[128];             // w128 @ bv
__device__ float  g_BM[NTOT * 16];
__device__ float  g_GW[4 * NSIDE];
__device__ float  g_P[128 * NTOT];

// ======================= helpers =======================
__device__ __forceinline__ uint32_t smem_u32(const void* p) {
    uint32_t a;
    asm("{ .reg .u64 t; cvta.to.shared.u64 t, %1; cvt.u32.u64 %0, t; }"
        : "=r"(a) : "l"(p));
    return a;
}
__device__ __forceinline__ void cp_async16(uint32_t dst, const void* src) {
    asm volatile("cp.async.cg.shared.global [%0], [%1], 16;" :: "r"(dst), "l"(src) : "memory");
}
#define CP_COMMIT() asm volatile("cp.async.commit_group;" ::: "memory")
#define CP_WAIT(n)  asm volatile("cp.async.wait_group %0;" :: "n"(n) : "memory")

__device__ __forceinline__ void mma_fp16(float* c, const uint32_t* a,
                                         uint32_t b0, uint32_t b1) {
    asm volatile(
        "mma.sync.aligned.m16n8k16.row.col.f32.f16.f16.f32 "
        "{%0,%1,%2,%3}, {%4,%5,%6,%7}, {%8,%9}, {%0,%1,%2,%3};"
        : "+f"(c[0]), "+f"(c[1]), "+f"(c[2]), "+f"(c[3])
        : "r"(a[0]), "r"(a[1]), "r"(a[2]), "r"(a[3]), "r"(b0), "r"(b1));
}

// ===========================================================================
// wcombT[c][o] = sum_k w128[o][k] * wv[k][c]   (fused projection weights)
// ===========================================================================
__global__ void combine_w_kernel(const float* __restrict__ w128,
                                 const float* __restrict__ wv) {
    int c = blockIdx.x, o = threadIdx.x;       // 256 blocks x 128 threads
    float s = 0.f;
    #pragma unroll 8
    for (int k = 0; k < 256; k++)
        s += w128[o * 256 + k] * wv[k * 256 + c];
    g_wcT[c * 128 + o] = s;
}

// pb2[o] = sum_c w128[o][c] * bv[c]
__global__ void pb2_kernel(const float* __restrict__ w128,
                           const float* __restrict__ bv) {
    int o = threadIdx.x;
    float s = 0.f;
    #pragma unroll 8
    for (int c = 0; c < 256; c++) s += w128[o * 256 + c] * bv[c];
    g_pb2[o] = s;
}

// ===========================================================================
// wq/wk -> fp16 [o][c], o in [0,512)
// ===========================================================================
__global__ void convert_wqk_kernel(const float* __restrict__ wq,
                                   const float* __restrict__ wk) {
    int o = blockIdx.x, c = threadIdx.x;
    float v = (o < 256) ? wq[o * 256 + c] : wk[(o - 256) * 256 + c];
    g_Whqk[o * 256 + c] = __float2half_rn(v);
}

// ===========================================================================
// x [b][c][hw] -> g_Xh [n][c] fp16 (tiled transpose)
// ===========================================================================
__global__ void convert_x_kernel(const float* __restrict__ x4,
                                 const float* __restrict__ x3) {
    __shared__ float tile[32][33];
    int z = blockIdx.z;
    int side = z >> 3, b = z & 7;
    const float* x = (side ? x3 : x4) + b * CDIM * HW;
    int hw0 = blockIdx.x * 32;
    int c0 = blockIdx.y * 32;
    int t = threadIdx.x;
    int lane = t & 31, ty = t >> 5;

    #pragma unroll
    for (int i = 0; i < 4; i++) {
        int cc = ty + i * 8;
        tile[cc][lane] = x[(c0 + cc) * HW + hw0 + lane];
    }
    __syncthreads();
    int nbase = side * NSIDE + b * HW + hw0;
    #pragma unroll
    for (int i = 0; i < 4; i++) {
        int hwr = ty + i * 8;
        g_Xh[(nbase + hwr) * 256 + c0 + lane] = __float2half_rn(tile[lane][hwr]);
    }
}

// ===========================================================================
// QK fp16 tensor GEMM: out[n][o] = sum_c Xh[n][c] * Whqk[o][c] + bias[o]
// ===========================================================================
#define QKG_SMEM (2 * 128 * 264 * 2)   // 135168 B

__global__ void __launch_bounds__(256, 1) qk_gemm_kernel(const float* __restrict__ bq,
                                                         const float* __restrict__ bk) {
    extern __shared__ __half smh[];
    __half* Xs = smh;              // 128 x 264
    __half* Ws = smh + 128 * 264;
    int t = threadIdx.x, lane = t & 31, wid = t >> 5;
    int wm = wid >> 2, wn = wid & 3;
    int grp = lane >> 2, qid = lane & 3;
    int m0 = blockIdx.x * 128, o0 = blockIdx.y * 128;

    uint32_t xb = smem_u32(Xs), wb = smem_u32(Ws);
    #pragma unroll
    for (int i = 0; i < 16; i++) {
        int s = t + i * 256;
        int row = s >> 5, seg = s & 31;
        cp_async16(xb + row * 528 + seg * 16,
                   (const char*)&g_Xh[(m0 + row) * 256] + seg * 16);
        cp_async16(wb + row * 528 + seg * 16,
                   (const char*)&g_Whqk[(o0 + row) * 256] + seg * 16);
    }
    CP_COMMIT(); CP_WAIT(0);
    __syncthreads();

    float acc[4][4][4] = {};
    #pragma unroll
    for (int kk = 0; kk < 16; kk++) {
        uint32_t a[4][4];
        #pragma unroll
        for (int rt = 0; rt < 4; rt++) {
            const __half* q0 = &Xs[(wm * 64 + rt * 16 + grp) * 264 + kk * 16 + qid * 2];
            a[rt][0] = *(const uint32_t*)q0;
            a[rt][1] = *(const uint32_t*)(q0 + 8 * 264);
            a[rt][2] = *(const uint32_t*)(q0 + 8);
            a[rt][3] = *(const uint32_t*)(q0 + 8 * 264 + 8);
        }
        #pragma unroll
        for (int nt = 0; nt < 4; nt++) {
            const __half* kp = &Ws[(wn * 32 + nt * 8 + grp) * 264 + kk * 16 + qid * 2];
            uint32_t b0 = *(const uint32_t*)kp;
            uint32_t b1 = *(const uint32_t*)(kp + 8);
            #pragma unroll
            for (int rt = 0; rt < 4; rt++)
                mma_fp16(acc[rt][nt], a[rt], b0, b1);
        }
    }

    __half* dst = (blockIdx.y < 2) ? g_Qh : g_Kh;
    const float* bias = (blockIdx.y < 2) ? bq : bk;
    #pragma unroll
    for (int rt = 0; rt < 4; rt++)
        #pragma unroll
        for (int nt = 0; nt < 4; nt++) {
            int col = (o0 + wn * 32 + nt * 8 + qid * 2) & 255;
            float b0f = bias[col], b1f = bias[col + 1];
            int r0 = m0 + wm * 64 + rt * 16 + grp;
            __half2 h0 = __floats2half2_rn(acc[rt][nt][0] + b0f, acc[rt][nt][1] + b1f);
            __half2 h1 = __floats2half2_rn(acc[rt][nt][2] + b0f, acc[rt][nt][3] + b1f);
            *(__half2*)&dst[r0 * 256 + col] = h0;
            *(__half2*)&dst[(r0 + 8) * 256 + col] = h1;
        }
}

// ===========================================================================
// fp16 tensor-core S block-max (unchanged from R4 — at mma.sync floor)
// ===========================================================================
#define QSH 264
#define KSH 40
#define KCH (128 * KSH)
#define SMAX_SMEM (128 * QSH * 2 + 4 * KCH * 2 + 1024)

__device__ __forceinline__ void load_k_chunk_h(uint32_t kb_base, int jbase, int cidx) {
    int jc = cidx >> 3, kc = cidx & 7;
    const __half* src = &g_Kh[(jbase + jc * 128) * 256 + kc * 32];
    int t = threadIdx.x;
    #pragma unroll
    for (int i = 0; i < 2; i++) {
        int s = t + i * 256;
        int row = s >> 2, seg = s & 3;
        cp_async16(kb_base + (uint32_t)(row * 80 + seg * 16),
                   (const char*)(src + row * 256) + seg * 16);
    }
    CP_COMMIT();
}

__global__ void __launch_bounds__(256, 2) smax_kernel() {
    extern __shared__ char sm[];
    __half* Qs = (__half*)sm;
    uint32_t qbase = smem_u32(sm);
    uint32_t kbase = qbase + 128 * QSH * 2;
    float* red = (float*)(sm + 128 * QSH * 2 + 4 * KCH * 2);

    int t = threadIdx.x, lane = t & 31, wid = t >> 5;
    int wr = wid >> 1, wc = wid & 1;
    int grp = lane >> 2, qid = lane & 3;
    int i0 = blockIdx.x * 128, kb = blockIdx.y, jbase = kb * HW;

    #pragma unroll
    for (int i = 0; i < 16; i++) {
        int s = t + i * 256;
        int row = s >> 5, seg = s & 31;
        cp_async16(qbase + (uint32_t)(row * 528 + seg * 16),
                   (const char*)&g_Qh[(i0 + row) * 256] + seg * 16);
    }
    CP_COMMIT();
    load_k_chunk_h(kbase + 0 * KCH * 2, jbase, 0);
    load_k_chunk_h(kbase + 1 * KCH * 2, jbase, 1);
    load_k_chunk_h(kbase + 2 * KCH * 2, jbase, 2);

    float rmax[2][2] = {{-1e30f, -1e30f}, {-1e30f, -1e30f}};
    float acc[2][8][4];

    for (int c = 0; c < 64; c++) {
        if (c <= 61) { CP_WAIT(2); }
        else if (c == 62) { CP_WAIT(1); }
        else { CP_WAIT(0); }
        __syncthreads();

        int kc = c & 7;
        const __half* kbuf = (const __half*)(sm + 128 * QSH * 2 + (size_t)(c & 3) * KCH * 2);

        if (kc == 0) {
            #pragma unroll
            for (int rt = 0; rt < 2; rt++)
                #pragma unroll
                for (int nt = 0; nt < 8; nt++)
                    #pragma unroll
                    for (int r = 0; r < 4; r++) acc[rt][nt][r] = 0.f;
        }

        #pragma unroll
        for (int s = 0; s < 2; s++) {
            int kcol = kc * 32 + s * 16;
            uint32_t a[2][4];
            #pragma unroll
            for (int rt = 0; rt < 2; rt++) {
                const __half* q0 = &Qs[(wr * 32 + rt * 16 + grp) * QSH + kcol + qid * 2];
                a[rt][0] = *(const uint32_t*)q0;
                a[rt][1] = *(const uint32_t*)(q0 + 8 * QSH);
                a[rt][2] = *(const uint32_t*)(q0 + 8);
                a[rt][3] = *(const uint32_t*)(q0 + 8 * QSH + 8);
            }
            #pragma unroll
            for (int nt = 0; nt < 8; nt++) {
                const __half* kp = &kbuf[(wc * 64 + nt * 8 + grp) * KSH + s * 16 + qid * 2];
                uint32_t b0 = *(const uint32_t*)kp;
                uint32_t b1 = *(const uint32_t*)(kp + 8);
                #pragma unroll
                for (int rt = 0; rt < 2; rt++)
                    mma_fp16(acc[rt][nt], a[rt], b0, b1);
            }
        }

        if (c + 3 < 64)
            load_k_chunk_h(kbase + (uint32_t)((c + 3) & 3) * KCH * 2, jbase, c + 3);

        if (kc == 7) {
            #pragma unroll
            for (int rt = 0; rt < 2; rt++)
                #pragma unroll
                for (int nt = 0; nt < 8; nt++) {
                    rmax[rt][0] = fmaxf(rmax[rt][0], fmaxf(acc[rt][nt][0], acc[rt][nt][1]));
                    rmax[rt][1] = fmaxf(rmax[rt][1], fmaxf(acc[rt][nt][2], acc[rt][nt][3]));
                }
        }
    }

    #pragma unroll
    for (int rt = 0; rt < 2; rt++)
        #pragma unroll
        for (int h = 0; h < 2; h++) {
            float v = rmax[rt][h];
            v = fmaxf(v, __shfl_xor_sync(0xFFFFFFFF, v, 1));
            v = fmaxf(v, __shfl_xor_sync(0xFFFFFFFF, v, 2));
            rmax[rt][h] = v;
        }

    __syncthreads();
    if (qid == 0) {
        #pragma unroll
        for (int rt = 0; rt < 2; rt++)
            #pragma unroll
            for (int h = 0; h < 2; h++) {
                int row = wr * 32 + rt * 16 + h * 8 + grp;
                red[wc * 128 + row] = rmax[rt][h];
            }
    }
    __syncthreads();
    if (t < 128)
        g_BM[(i0 + t) * 16 + kb] = fmaxf(red[t], red[128 + t]);
}

// ===========================================================================
// Gate: softmax over 1024 of mean-of-8-blockmax * scale
// ===========================================================================
__global__ void gate_kernel() {
    int g = blockIdx.x >> 3;
    int b = blockIdx.x & 7;
    int side = (g == 0 || g == 2) ? 0 : 1;
    int kbb  = (g == 0 || g == 3) ? 0 : 8;
    int irow = side * NSIDE + b * HW;
    int t = threadIdx.x;

    float vals[4];
    #pragma unroll
    for (int r = 0; r < 4; r++) {
        int hw = t + 256 * r;
        const float* bm = &g_BM[(irow + hw) * 16 + kbb];
        float s = 0.f;
        #pragma unroll
        for (int k = 0; k < 8; k++) s += bm[k];
        vals[r] = s * (0.0625f / 8.0f);
    }
    __shared__ float red[256];
    float mx = fmaxf(fmaxf(vals[0], vals[1]), fmaxf(vals[2], vals[3]));
    red[t] = mx; __syncthreads();
    for (int s2 = 128; s2 > 0; s2 >>= 1) {
        if (t < s2) red[t] = fmaxf(red[t], red[t + s2]);
        __syncthreads();
    }
    mx = red[0]; __syncthreads();
    float sum = 0.f;
    #pragma unroll
    for (int r = 0; r < 4; r++) { vals[r] = expf(vals[r] - mx); sum += vals[r]; }
    red[t] = sum; __syncthreads();
    for (int s2 = 128; s2 > 0; s2 >>= 1) {
        if (t < s2) red[t] += red[t + s2];
        __syncthreads();
    }
    float inv = 1.f / red[0];
    #pragma unroll
    for (int r = 0; r < 4; r++)
        g_GW[g * NSIDE + b * HW + t + 256 * r] = vals[r] * inv;
}

// ===========================================================================
// Fused projection: P[o][n] = sum_c wcT[c][o] * x[.][c][hw] + pb2[o]
// 64(n) x 64(o) tiles, fp32 SIMT. grid (256 n-tiles, 2 o-tiles).
// ===========================================================================
__global__ void pcomb_kernel(const float* __restrict__ x4,
                             const float* __restrict__ x3) {
    int n0 = blockIdx.x * 64;
    int side = n0 >> 13;
    int rem = n0 & (NSIDE - 1);
    int b = rem >> 10;
    int hw0 = rem & (HW - 1);
    const float* x = (side ? x3 : x4) + b * CDIM * HW;
    int o0 = blockIdx.y * 64;

    __shared__ float Xs[16][64];   // [cc][nn]
    __shared__ float Ws[16][64];   // [cc][oo]
    int t = threadIdx.x;
    int tx = t & 15, ty = t >> 4;
    float acc[4][4] = {};          // [o r][n c2]

    for (int c0 = 0; c0 < CDIM; c0 += 16) {
        #pragma unroll
        for (int r = 0; r < 4; r++) {
            int idx = r * 256 + t;
            int cc = idx >> 6, nn = idx & 63;
            Xs[cc][nn] = x[(c0 + cc) * HW + hw0 + nn];
            Ws[cc][nn] = g_wcT[(c0 + cc) * 128 + o0 + nn];
        }
        __syncthreads();
        #pragma unroll
        for (int kk = 0; kk < 16; kk++) {
            float4 o4 = *(const float4*)&Ws[kk][ty * 4];
            float4 n4 = *(const float4*)&Xs[kk][tx * 4];
            float oo[4] = {o4.x, o4.y, o4.z, o4.w};
            float nn[4] = {n4.x, n4.y, n4.z, n4.w};
            #pragma unroll
            for (int r = 0; r < 4; r++)
                #pragma unroll
                for (int c2 = 0; c2 < 4; c2++)
                    acc[r][c2] += oo[r] * nn[c2];
        }
        __syncthreads();
    }
    #pragma unroll
    for (int r = 0; r < 4; r++) {
        int o = o0 + ty * 4 + r;
        float pb = g_pb2[o];
        float4 v;
        v.x = acc[r][0] + pb; v.y = acc[r][1] + pb;
        v.z = acc[r][2] + pb; v.w = acc[r][3] + pb;
        *(float4*)&g_P[o * NTOT + n0 + tx * 4] = v;
    }
}

// ===========================================================================
// Final: out = gate * P + b128
// ===========================================================================
__global__ void final_kernel(const float* __restrict__ b128, float* __restrict__ out) {
    int idx = blockIdx.x * 256 + threadIdx.x;
    int hw = idx & (HW - 1);
    int ch = (idx >> 10) & 511;
    int b = idx >> 19;
    int n = b * HW + hw;
    int br = ch >> 7;
    int o = ch & 127;
    int gidx  = (br == 0) ? 3 : (br == 1) ? 0 : (br == 2) ? 2 : 1;
    int pside = (br < 2) ? 0 : 1;
    float gv = g_GW[gidx * NSIDE + n];
    float pv = g_P[o * NTOT + pside * NSIDE + n];
    out[idx] = gv * pv + b128[o];
}

extern "C" void kernel_launch(void* const* d_in, const int* in_sizes, int n_in,
                              void* d_out, int out_size) {
    const float* x4   = (const float*)d_in[0];
    const float* x3   = (const float*)d_in[1];
    const float* wq   = (const float*)d_in[2];
    const float* bq   = (const float*)d_in[3];
    const float* wk   = (const float*)d_in[4];
    const float* bk   = (const float*)d_in[5];
    const float* wv   = (const float*)d_in[6];
    const float* bv   = (const float*)d_in[7];
    const float* w128 = (const float*)d_in[8];
    const float* b128 = (const float*)d_in[9];
    float* out = (float*)d_out;

    static int attr_set = 0;
    if (!attr_set) {
        cudaFuncSetAttribute(smax_kernel,
                             cudaFuncAttributeMaxDynamicSharedMemorySize, SMAX_SMEM);
        cudaFuncSetAttribute(qk_gemm_kernel,
                             cudaFuncAttributeMaxDynamicSharedMemorySize, QKG_SMEM);
        attr_set = 1;
    }

    combine_w_kernel<<<256, 128>>>(w128, wv);
    pb2_kernel<<<1, 128>>>(w128, bv);
    convert_wqk_kernel<<<512, 256>>>(wq, wk);
    convert_x_kernel<<<dim3(32, 8, 16), 256>>>(x4, x3);
    qk_gemm_kernel<<<dim3(128, 4), 256, QKG_SMEM>>>(bq, bk);
    pcomb_kernel<<<dim3(256, 2), 256>>>(x4, x3);
    smax_kernel<<<dim3(128, 16), 256, SMAX_SMEM>>>();
    gate_kernel<<<32, 256>>>();
    final_kernel<<<16384, 256>>>(b128, out);
}

// round 7
// speedup vs baseline: 9.4378x; 1.0609x over previous
#include <cuda_runtime.h>
#include <cuda_fp16.h>
#include <cstdint>

#define HW 1024
#define CDIM 256
#define NSIDE 8192
#define NTOT 16384

// -------- scratch (device globals; no allocation allowed) --------
__device__ __half g_Xh[NTOT * CDIM];      // x transposed to [n][c], fp16
__device__ __half g_Whqk[512 * CDIM];     // [wq;wk] as [o][c], fp16
__device__ __half g_Qh[NTOT * CDIM];
__device__ __half g_Kh[NTOT * CDIM];
__device__ float  g_wcT[CDIM * 128];      // (w128 @ wv) transposed [c][o]
__device__ float  g_pb2[128];             // w128 @ bv
__device__ float  g_BM[NTOT * 16];
__device__ float  g_GW[4 * NSIDE];
__device__ float  g_P[128 * NTOT];

// ======================= helpers =======================
__device__ __forceinline__ uint32_t smem_u32(const void* p) {
    uint32_t a;
    asm("{ .reg .u64 t; cvta.to.shared.u64 t, %1; cvt.u32.u64 %0, t; }"
        : "=r"(a) : "l"(p));
    return a;
}
__device__ __forceinline__ void cp_async16(uint32_t dst, const void* src) {
    asm volatile("cp.async.cg.shared.global [%0], [%1], 16;" :: "r"(dst), "l"(src) : "memory");
}
#define CP_COMMIT() asm volatile("cp.async.commit_group;" ::: "memory")
#define CP_WAIT(n)  asm volatile("cp.async.wait_group %0;" :: "n"(n) : "memory")

__device__ __forceinline__ void mma_fp16(float* c, const uint32_t* a,
                                         uint32_t b0, uint32_t b1) {
    asm volatile(
        "mma.sync.aligned.m16n8k16.row.col.f32.f16.f16.f32 "
        "{%0,%1,%2,%3}, {%4,%5,%6,%7}, {%8,%9}, {%0,%1,%2,%3};"
        : "+f"(c[0]), "+f"(c[1]), "+f"(c[2]), "+f"(c[3])
        : "r"(a[0]), "r"(a[1]), "r"(a[2]), "r"(a[3]), "r"(b0), "r"(b1));
}
__device__ __forceinline__ void ldsm_x4(uint32_t* r, uint32_t addr) {
    asm volatile("ldmatrix.sync.aligned.m8n8.x4.shared.b16 {%0,%1,%2,%3}, [%4];"
        : "=r"(r[0]), "=r"(r[1]), "=r"(r[2]), "=r"(r[3]) : "r"(addr));
}
__device__ __forceinline__ void ldsm_x2(uint32_t& r0, uint32_t& r1, uint32_t addr) {
    asm volatile("ldmatrix.sync.aligned.m8n8.x2.shared.b16 {%0,%1}, [%2];"
        : "=r"(r0), "=r"(r1) : "r"(addr));
}

// ===========================================================================
// wcombT[c][o] = sum_k w128[o][k] * wv[k][c]
// ===========================================================================
__global__ void combine_w_kernel(const float* __restrict__ w128,
                                 const float* __restrict__ wv) {
    int c = blockIdx.x, o = threadIdx.x;
    float s = 0.f;
    #pragma unroll 8
    for (int k = 0; k < 256; k++)
        s += w128[o * 256 + k] * wv[k * 256 + c];
    g_wcT[c * 128 + o] = s;
}

__global__ void pb2_kernel(const float* __restrict__ w128,
                           const float* __restrict__ bv) {
    int o = threadIdx.x;
    float s = 0.f;
    #pragma unroll 8
    for (int c = 0; c < 256; c++) s += w128[o * 256 + c] * bv[c];
    g_pb2[o] = s;
}

// ===========================================================================
// wq/wk -> fp16 [o][c]
// ===========================================================================
__global__ void convert_wqk_kernel(const float* __restrict__ wq,
                                   const float* __restrict__ wk) {
    int o = blockIdx.x, c = threadIdx.x;
    float v = (o < 256) ? wq[o * 256 + c] : wk[(o - 256) * 256 + c];
    g_Whqk[o * 256 + c] = __float2half_rn(v);
}

// ===========================================================================
// x [b][c][hw] -> g_Xh [n][c] fp16 (tiled transpose)
// ===========================================================================
__global__ void convert_x_kernel(const float* __restrict__ x4,
                                 const float* __restrict__ x3) {
    __shared__ float tile[32][33];
    int z = blockIdx.z;
    int side = z >> 3, b = z & 7;
    const float* x = (side ? x3 : x4) + b * CDIM * HW;
    int hw0 = blockIdx.x * 32;
    int c0 = blockIdx.y * 32;
    int t = threadIdx.x;
    int lane = t & 31, ty = t >> 5;

    #pragma unroll
    for (int i = 0; i < 4; i++) {
        int cc = ty + i * 8;
        tile[cc][lane] = x[(c0 + cc) * HW + hw0 + lane];
    }
    __syncthreads();
    int nbase = side * NSIDE + b * HW + hw0;
    #pragma unroll
    for (int i = 0; i < 4; i++) {
        int hwr = ty + i * 8;
        g_Xh[(nbase + hwr) * 256 + c0 + lane] = __float2half_rn(tile[lane][hwr]);
    }
}

// ===========================================================================
// QK fp16 tensor GEMM
// ===========================================================================
#define QKG_SMEM (2 * 128 * 264 * 2)

__global__ void __launch_bounds__(256, 1) qk_gemm_kernel(const float* __restrict__ bq,
                                                         const float* __restrict__ bk) {
    extern __shared__ __half smh[];
    __half* Xs = smh;
    __half* Ws = smh + 128 * 264;
    int t = threadIdx.x, lane = t & 31, wid = t >> 5;
    int wm = wid >> 2, wn = wid & 3;
    int grp = lane >> 2, qid = lane & 3;
    int m0 = blockIdx.x * 128, o0 = blockIdx.y * 128;

    uint32_t xb = smem_u32(Xs), wb = smem_u32(Ws);
    #pragma unroll
    for (int i = 0; i < 16; i++) {
        int s = t + i * 256;
        int row = s >> 5, seg = s & 31;
        cp_async16(xb + row * 528 + seg * 16,
                   (const char*)&g_Xh[(m0 + row) * 256] + seg * 16);
        cp_async16(wb + row * 528 + seg * 16,
                   (const char*)&g_Whqk[(o0 + row) * 256] + seg * 16);
    }
    CP_COMMIT(); CP_WAIT(0);
    __syncthreads();

    float acc[4][4][4] = {};
    #pragma unroll
    for (int kk = 0; kk < 16; kk++) {
        uint32_t a[4][4];
        #pragma unroll
        for (int rt = 0; rt < 4; rt++) {
            const __half* q0 = &Xs[(wm * 64 + rt * 16 + grp) * 264 + kk * 16 + qid * 2];
            a[rt][0] = *(const uint32_t*)q0;
            a[rt][1] = *(const uint32_t*)(q0 + 8 * 264);
            a[rt][2] = *(const uint32_t*)(q0 + 8);
            a[rt][3] = *(const uint32_t*)(q0 + 8 * 264 + 8);
        }
        #pragma unroll
        for (int nt = 0; nt < 4; nt++) {
            const __half* kp = &Ws[(wn * 32 + nt * 8 + grp) * 264 + kk * 16 + qid * 2];
            uint32_t b0 = *(const uint32_t*)kp;
            uint32_t b1 = *(const uint32_t*)(kp + 8);
            #pragma unroll
            for (int rt = 0; rt < 4; rt++)
                mma_fp16(acc[rt][nt], a[rt], b0, b1);
        }
    }

    __half* dst = (blockIdx.y < 2) ? g_Qh : g_Kh;
    const float* bias = (blockIdx.y < 2) ? bq : bk;
    #pragma unroll
    for (int rt = 0; rt < 4; rt++)
        #pragma unroll
        for (int nt = 0; nt < 4; nt++) {
            int col = (o0 + wn * 32 + nt * 8 + qid * 2) & 255;
            float b0f = bias[col], b1f = bias[col + 1];
            int r0 = m0 + wm * 64 + rt * 16 + grp;
            __half2 h0 = __floats2half2_rn(acc[rt][nt][0] + b0f, acc[rt][nt][1] + b1f);
            __half2 h1 = __floats2half2_rn(acc[rt][nt][2] + b0f, acc[rt][nt][3] + b1f);
            *(__half2*)&dst[r0 * 256 + col] = h0;
            *(__half2*)&dst[(r0 + 8) * 256 + col] = h1;
        }
}

// ===========================================================================
// fp16 tensor-core S block-max, ldmatrix operand feeding.
// ===========================================================================
#define QSH 264
#define KSH 40
#define KCH (128 * KSH)
#define SMAX_SMEM (128 * QSH * 2 + 4 * KCH * 2 + 1024)

__device__ __forceinline__ void load_k_chunk_h(uint32_t kb_base, int jbase, int cidx) {
    int jc = cidx >> 3, kc = cidx & 7;
    const __half* src = &g_Kh[(jbase + jc * 128) * 256 + kc * 32];
    int t = threadIdx.x;
    #pragma unroll
    for (int i = 0; i < 2; i++) {
        int s = t + i * 256;
        int row = s >> 2, seg = s & 3;
        cp_async16(kb_base + (uint32_t)(row * 80 + seg * 16),
                   (const char*)(src + row * 256) + seg * 16);
    }
    CP_COMMIT();
}

__global__ void __launch_bounds__(256, 2) smax_kernel() {
    extern __shared__ char sm[];
    uint32_t qbase = smem_u32(sm);
    uint32_t kbase = qbase + 128 * QSH * 2;
    float* red = (float*)(sm + 128 * QSH * 2 + 4 * KCH * 2);

    int t = threadIdx.x, lane = t & 31, wid = t >> 5;
    int wr = wid >> 1, wc = wid & 1;
    int grp = lane >> 2, qid = lane & 3;
    int i0 = blockIdx.x * 128, kb = blockIdx.y, jbase = kb * HW;

    // Q tile -> smem (group 0)
    #pragma unroll
    for (int i = 0; i < 16; i++) {
        int s = t + i * 256;
        int row = s >> 5, seg = s & 31;
        cp_async16(qbase + (uint32_t)(row * 528 + seg * 16),
                   (const char*)&g_Qh[(i0 + row) * 256] + seg * 16);
    }
    CP_COMMIT();
    load_k_chunk_h(kbase + 0 * KCH * 2, jbase, 0);
    load_k_chunk_h(kbase + 1 * KCH * 2, jbase, 1);
    load_k_chunk_h(kbase + 2 * KCH * 2, jbase, 2);

    // ldmatrix base addresses
    uint32_t qa = qbase + (uint32_t)(((wr * 32 + (lane & 15)) * QSH + (lane >> 4) * 8) * 2);
    uint32_t kboff = (uint32_t)(((wc * 64 + (lane & 7)) * KSH + ((lane >> 3) & 1) * 8) * 2);

    float rmax[2][2] = {{-1e30f, -1e30f}, {-1e30f, -1e30f}};
    float acc[2][8][4];

    for (int c = 0; c < 64; c++) {
        if (c <= 61) { CP_WAIT(2); }
        else if (c == 62) { CP_WAIT(1); }
        else { CP_WAIT(0); }
        __syncthreads();

        int kc = c & 7;
        uint32_t kbuf = kbase + (uint32_t)(c & 3) * (KCH * 2) + kboff;
        uint32_t qac = qa + (uint32_t)(kc * 64);      // kc*32 halves = 64 B

        if (kc == 0) {
            #pragma unroll
            for (int rt = 0; rt < 2; rt++)
                #pragma unroll
                for (int nt = 0; nt < 8; nt++)
                    #pragma unroll
                    for (int r = 0; r < 4; r++) acc[rt][nt][r] = 0.f;
        }

        #pragma unroll
        for (int s = 0; s < 2; s++) {
            uint32_t a0[4], a1[4];
            ldsm_x4(a0, qac + s * 32);
            ldsm_x4(a1, qac + s * 32 + 16 * QSH * 2);
            #pragma unroll
            for (int nt = 0; nt < 8; nt++) {
                uint32_t b0, b1;
                ldsm_x2(b0, b1, kbuf + (uint32_t)(nt * 8 * KSH * 2) + s * 32);
                mma_fp16(acc[0][nt], a0, b0, b1);
                mma_fp16(acc[1][nt], a1, b0, b1);
            }
        }

        if (c + 3 < 64)
            load_k_chunk_h(kbase + (uint32_t)((c + 3) & 3) * (KCH * 2), jbase, c + 3);

        if (kc == 7) {
            #pragma unroll
            for (int rt = 0; rt < 2; rt++)
                #pragma unroll
                for (int nt = 0; nt < 8; nt++) {
                    rmax[rt][0] = fmaxf(rmax[rt][0], fmaxf(acc[rt][nt][0], acc[rt][nt][1]));
                    rmax[rt][1] = fmaxf(rmax[rt][1], fmaxf(acc[rt][nt][2], acc[rt][nt][3]));
                }
        }
    }

    #pragma unroll
    for (int rt = 0; rt < 2; rt++)
        #pragma unroll
        for (int h = 0; h < 2; h++) {
            float v = rmax[rt][h];
            v = fmaxf(v, __shfl_xor_sync(0xFFFFFFFF, v, 1));
            v = fmaxf(v, __shfl_xor_sync(0xFFFFFFFF, v, 2));
            rmax[rt][h] = v;
        }

    __syncthreads();
    if (qid == 0) {
        #pragma unroll
        for (int rt = 0; rt < 2; rt++)
            #pragma unroll
            for (int h = 0; h < 2; h++) {
                int row = wr * 32 + rt * 16 + h * 8 + grp;
                red[wc * 128 + row] = rmax[rt][h];
            }
    }
    __syncthreads();
    if (t < 128)
        g_BM[(i0 + t) * 16 + kb] = fmaxf(red[t], red[128 + t]);
}

// ===========================================================================
// Gate: softmax over 1024 of mean-of-8-blockmax * scale
// ===========================================================================
__global__ void gate_kernel() {
    int g = blockIdx.x >> 3;
    int b = blockIdx.x & 7;
    int side = (g == 0 || g == 2) ? 0 : 1;
    int kbb  = (g == 0 || g == 3) ? 0 : 8;
    int irow = side * NSIDE + b * HW;
    int t = threadIdx.x;

    float vals[4];
    #pragma unroll
    for (int r = 0; r < 4; r++) {
        int hw = t + 256 * r;
        const float* bm = &g_BM[(irow + hw) * 16 + kbb];
        float s = 0.f;
        #pragma unroll
        for (int k = 0; k < 8; k++) s += bm[k];
        vals[r] = s * (0.0625f / 8.0f);
    }
    __shared__ float red[256];
    float mx = fmaxf(fmaxf(vals[0], vals[1]), fmaxf(vals[2], vals[3]));
    red[t] = mx; __syncthreads();
    for (int s2 = 128; s2 > 0; s2 >>= 1) {
        if (t < s2) red[t] = fmaxf(red[t], red[t + s2]);
        __syncthreads();
    }
    mx = red[0]; __syncthreads();
    float sum = 0.f;
    #pragma unroll
    for (int r = 0; r < 4; r++) { vals[r] = expf(vals[r] - mx); sum += vals[r]; }
    red[t] = sum; __syncthreads();
    for (int s2 = 128; s2 > 0; s2 >>= 1) {
        if (t < s2) red[t] += red[t + s2];
        __syncthreads();
    }
    float inv = 1.f / red[0];
    #pragma unroll
    for (int r = 0; r < 4; r++)
        g_GW[g * NSIDE + b * HW + t + 256 * r] = vals[r] * inv;
}

// ===========================================================================
// Fused projection: P[o][n] = sum_c wcT[c][o] * x[.][c][hw] + pb2[o]
// ===========================================================================
__global__ void pcomb_kernel(const float* __restrict__ x4,
                             const float* __restrict__ x3) {
    int n0 = blockIdx.x * 64;
    int side = n0 >> 13;
    int rem = n0 & (NSIDE - 1);
    int b = rem >> 10;
    int hw0 = rem & (HW - 1);
    const float* x = (side ? x3 : x4) + b * CDIM * HW;
    int o0 = blockIdx.y * 64;

    __shared__ float Xs[16][64];
    __shared__ float Ws[16][64];
    int t = threadIdx.x;
    int tx = t & 15, ty = t >> 4;
    float acc[4][4] = {};

    for (int c0 = 0; c0 < CDIM; c0 += 16) {
        #pragma unroll
        for (int r = 0; r < 4; r++) {
            int idx = r * 256 + t;
            int cc = idx >> 6, nn = idx & 63;
            Xs[cc][nn] = x[(c0 + cc) * HW + hw0 + nn];
            Ws[cc][nn] = g_wcT[(c0 + cc) * 128 + o0 + nn];
        }
        __syncthreads();
        #pragma unroll
        for (int kk = 0; kk < 16; kk++) {
            float4 o4 = *(const float4*)&Ws[kk][ty * 4];
            float4 n4 = *(const float4*)&Xs[kk][tx * 4];
            float oo[4] = {o4.x, o4.y, o4.z, o4.w};
            float nn[4] = {n4.x, n4.y, n4.z, n4.w};
            #pragma unroll
            for (int r = 0; r < 4; r++)
                #pragma unroll
                for (int c2 = 0; c2 < 4; c2++)
                    acc[r][c2] += oo[r] * nn[c2];
        }
        __syncthreads();
    }
    #pragma unroll
    for (int r = 0; r < 4; r++) {
        int o = o0 + ty * 4 + r;
        float pb = g_pb2[o];
        float4 v;
        v.x = acc[r][0] + pb; v.y = acc[r][1] + pb;
        v.z = acc[r][2] + pb; v.w = acc[r][3] + pb;
        *(float4*)&g_P[o * NTOT + n0 + tx * 4] = v;
    }
}

// ===========================================================================
// Final: out = gate * P + b128  (float4, 4 elems/thread, grid 4096)
// ===========================================================================
__global__ void final_kernel(const float* __restrict__ b128, float* __restrict__ out) {
    int idx4 = (blockIdx.x * 256 + threadIdx.x) * 4;
    int hw = idx4 & (HW - 1);
    int ch = (idx4 >> 10) & 511;
    int b = idx4 >> 19;
    int n = b * HW + hw;
    int br = ch >> 7;
    int o = ch & 127;
    int gidx  = (br == 0) ? 3 : (br == 1) ? 0 : (br == 2) ? 2 : 1;
    int pside = (br < 2) ? 0 : 1;
    float4 gv = *(const float4*)&g_GW[gidx * NSIDE + n];
    float4 pv = *(const float4*)&g_P[o * NTOT + pside * NSIDE + n];
    float bb = b128[o];
    float4 ov;
    ov.x = gv.x * pv.x + bb; ov.y = gv.y * pv.y + bb;
    ov.z = gv.z * pv.z + bb; ov.w = gv.w * pv.w + bb;
    *(float4*)&out[idx4] = ov;
}

extern "C" void kernel_launch(void* const* d_in, const int* in_sizes, int n_in,
                              void* d_out, int out_size) {
    const float* x4   = (const float*)d_in[0];
    const float* x3   = (const float*)d_in[1];
    const float* wq   = (const float*)d_in[2];
    const float* bq   = (const float*)d_in[3];
    const float* wk   = (const float*)d_in[4];
    const float* bk   = (const float*)d_in[5];
    const float* wv   = (const float*)d_in[6];
    const float* bv   = (const float*)d_in[7];
    const float* w128 = (const float*)d_in[8];
    const float* b128 = (const float*)d_in[9];
    float* out = (float*)d_out;

    static int attr_set = 0;
    if (!attr_set) {
        cudaFuncSetAttribute(smax_kernel,
                             cudaFuncAttributeMaxDynamicSharedMemorySize, SMAX_SMEM);
        cudaFuncSetAttribute(qk_gemm_kernel,
                             cudaFuncAttributeMaxDynamicSharedMemorySize, QKG_SMEM);
        attr_set = 1;
    }

    combine_w_kernel<<<256, 128>>>(w128, wv);
    pb2_kernel<<<1, 128>>>(w128, bv);
    convert_wqk_kernel<<<512, 256>>>(wq, wk);
    convert_x_kernel<<<dim3(32, 8, 16), 256>>>(x4, x3);
    qk_gemm_kernel<<<dim3(128, 4), 256, QKG_SMEM>>>(bq, bk);
    pcomb_kernel<<<dim3(256, 2), 256>>>(x4, x3);
    smax_kernel<<<dim3(128, 16), 256, SMAX_SMEM>>>();
    gate_kernel<<<32, 256>>>();
    final_kernel<<<4096, 256>>>(b128, out);
}